// round 11
// baseline (speedup 1.0000x reference)
#include <cuda_runtime.h>
#include <cuda_bf16.h>
#include <math.h>

// Fallback scratch + per-batch accumulation state (zero-init; finalizer
// restores zeros each run so graph replays stay deterministic).
__device__ float g_maxscore[1 << 19];
__device__ float g_score_part[4096];
__device__ unsigned g_count[4096];

__device__ __forceinline__ unsigned f2ord(float x) {
    unsigned b = __float_as_uint(x);
    return (b & 0x80000000u) ? ~b : (b | 0x80000000u);
}
__device__ __forceinline__ float ord2f(unsigned u) {
    return __uint_as_float((u & 0x80000000u) ? (u ^ 0x80000000u) : ~u);
}
__device__ __forceinline__ unsigned smem_u32(const void* p) {
    unsigned a;
    asm("{ .reg .u64 t; cvta.to.shared.u64 t, %1; cvt.u32.u64 %0, t; }"
        : "=r"(a) : "l"(p));
    return a;
}
__device__ __forceinline__ void mbar_wait0(unsigned mbar) {
    asm volatile(
        "{\n\t.reg .pred P;\n\t"
        "W_%=:\n\t"
        "mbarrier.try_wait.parity.shared.b64 P, [%0], 0;\n\t"
        "@P bra D_%=;\n\t"
        "bra W_%=;\n\t"
        "D_%=:\n\t}"
        :: "r"(mbar) : "memory");
}

// Exact warp argmax (first index) over 128 values held as float4/lane.
__device__ __forceinline__ int warp_argmax128(float4 v, int lane, unsigned* Mu_out) {
    float m = v.x; int mi = 0;
    if (v.y > m) { m = v.y; mi = 1; }
    if (v.z > m) { m = v.z; mi = 2; }
    if (v.w > m) { m = v.w; mi = 3; }
    mi += lane * 4;
    unsigned mu = f2ord(m);
    unsigned Mu = __reduce_max_sync(0xFFFFFFFFu, mu);
    unsigned cand = (mu == Mu) ? (unsigned)mi : 0xFFFFFFFFu;
    *Mu_out = Mu;
    return (int)__reduce_min_sync(0xFFFFFFFFu, cand);
}

// ---------------------------------------------------------------------------
// Fused TMA kernel (V=128, T%64==0): block = 256 threads = 8 warps = 64 rows.
// One cp.async.bulk per block stages rows [R-1, R+64) into smem (no register
// cost, deep TMA pipelining; 6 CTAs/SM stagger load/compute phases). Compute
// from smem: exact two-REDUX argmax, unshifted exp + fixed-point REDUX.ADD.
// keep via smem tokens. score: per-batch finalize with acq_rel fences,
// self-resetting (graph-replay safe, single launch).
// ---------------------------------------------------------------------------
__global__ void __launch_bounds__(256) ctc_fused_tma(
    const float* __restrict__ feat, const int* __restrict__ lengths,
    float* __restrict__ tok_out, float* __restrict__ keep_out,
    float* __restrict__ score_out, int T, int blocksPerBatch)
{
    __shared__ alignas(16) float s_feat[65 * 128];   // row j holds global row R-1+j
    __shared__ int   s_tok[65];
    __shared__ float s_score;
    __shared__ alignas(8) unsigned long long s_mbar;

    const int tid  = threadIdx.x;
    const int lane = tid & 31;
    const int w    = tid >> 5;
    const int R    = blockIdx.x * 64;
    const int b    = R / T;
    const int tb   = R - b * T;

    const unsigned mbar = smem_u32(&s_mbar);
    if (tid == 0) {
        s_score = 0.f;
        asm volatile("mbarrier.init.shared.b64 [%0], 1;" :: "r"(mbar) : "memory");
    }
    __syncthreads();

    if (tid == 0) {
        const char* src;
        unsigned dst, bytes;
        if (R > 0) {            // include boundary row R-1
            src = (const char*)(feat + (size_t)(R - 1) * 128);
            dst = smem_u32(s_feat);
            bytes = 65u * 512u;
        } else {                // block 0: no row -1 exists
            src = (const char*)feat;
            dst = smem_u32(s_feat) + 512u;
            bytes = 64u * 512u;
        }
        asm volatile("mbarrier.arrive.expect_tx.shared.b64 _, [%0], %1;"
                     :: "r"(mbar), "r"(bytes) : "memory");
        asm volatile(
            "cp.async.bulk.shared::cta.global.mbarrier::complete_tx::bytes "
            "[%0], [%1], %2, [%3];"
            :: "r"(dst), "l"(src), "r"(bytes), "r"(mbar) : "memory");
    }

    const int len = lengths[b];              // overlap with TMA

    mbar_wait0(mbar);

    // Boundary token (smem row 0 = global row R-1), warp 0. BLANK at batch start.
    if (w == 0) {
        int bt = 0;
        if (tb != 0) {
            unsigned Mu;
            float4 vb = reinterpret_cast<const float4*>(s_feat)[lane];
            bt = warp_argmax128(vb, lane, &Mu);
        }
        if (lane == 0) s_tok[0] = bt;
    }

    const int nvalid = len - (tb + w * 8);   // rows [0,nvalid) of group valid
    float acc = 0.f;
    const float4* sf4 = reinterpret_cast<const float4*>(s_feat);
    #pragma unroll
    for (int r = 0; r < 8; r++) {
        float4 v = sf4[(1 + w * 8 + r) * 32 + lane];
        unsigned Mu;
        int token = warp_argmax128(v, lane, &Mu);
        if (lane == 0) s_tok[1 + w * 8 + r] = token;

        if (r < nvalid) {                    // warp-uniform
            float s = __expf(v.x) + __expf(v.y) + __expf(v.z) + __expf(v.w);
            unsigned fx = (unsigned)(s * 65536.0f);
            unsigned S = __reduce_add_sync(0xFFFFFFFFu, fx);
            // max(log_softmax) = M - log(S * 2^-16) = M - log(S) + 16 ln2
            acc += ord2f(Mu) - __logf((float)S) + 11.0903548889591f;
        }
    }
    if (lane == 0 && nvalid > 0) atomicAdd(&s_score, acc);

    __syncthreads();

    // tok + keep for the block's 64 rows.
    if (tid < 64) {
        int cur  = s_tok[1 + tid];
        int prev = s_tok[tid];
        int t = tb + tid;
        tok_out[R + tid]  = (float)cur;
        keep_out[R + tid] = (cur != 0 && cur != prev && t < len) ? 1.f : 0.f;
    }

    if (tid == 0) {
        asm volatile("mbarrier.inval.shared.b64 [%0];" :: "r"(mbar) : "memory");
        // Per-batch score finalize: release add, acquire via counter, re-read.
        atomicAdd(&g_score_part[b], s_score);
        asm volatile("fence.acq_rel.gpu;" ::: "memory");
        unsigned old = atomicAdd(&g_count[b], 1u);
        if (old == (unsigned)(blocksPerBatch - 1)) {
            asm volatile("fence.acq_rel.gpu;" ::: "memory");
            float total = *((volatile float*)&g_score_part[b]);
            score_out[b] = total;
            g_score_part[b] = 0.f;           // restore for next replay
            asm volatile("fence.acq_rel.gpu;" ::: "memory");
            g_count[b] = 0u;
        }
    }
}

// ---------------------------------------------------------------------------
// Generic fallbacks (any V / T). Not expected to run for this shape.
// ---------------------------------------------------------------------------
__global__ void ctc_pass1_gen(const float* __restrict__ feat,
                              float* __restrict__ tok_out,
                              int rows, int V) {
    int warp = (blockIdx.x * blockDim.x + threadIdx.x) >> 5;
    int lane = threadIdx.x & 31;
    if (warp >= rows) return;
    const float* row = feat + (size_t)warp * V;

    float m = -INFINITY; int mi = 0;
    for (int i = lane; i < V; i += 32) {
        float x = row[i];
        if (x > m) { m = x; mi = i; }
    }
    #pragma unroll
    for (int o = 16; o; o >>= 1) {
        float om = __shfl_xor_sync(0xFFFFFFFFu, m, o);
        int   oi = __shfl_xor_sync(0xFFFFFFFFu, mi, o);
        if (om > m || (om == m && oi < mi)) { m = om; mi = oi; }
    }
    float s = 0.f;
    for (int i = lane; i < V; i += 32) s += __expf(row[i] - m);
    #pragma unroll
    for (int o = 16; o; o >>= 1) s += __shfl_xor_sync(0xFFFFFFFFu, s, o);
    if (lane == 0) { tok_out[warp] = (float)mi; g_maxscore[warp] = -__logf(s); }
}

__global__ void ctc_pass2_gen(const float* __restrict__ tok,
                              const int* __restrict__ lengths,
                              float* __restrict__ keep_out,
                              float* __restrict__ score_out,
                              int T) {
    int b = blockIdx.x;
    int len = lengths[b];
    const float* trow = tok + (size_t)b * T;
    float* krow = keep_out + (size_t)b * T;
    const float* srow = g_maxscore + (size_t)b * T;

    float acc = 0.f;
    for (int t = threadIdx.x; t < T; t += blockDim.x) {
        int cur  = (int)trow[t];
        int prev = (t == 0) ? 0 : (int)trow[t - 1];
        bool valid = (t < len);
        krow[t] = (cur != 0 && cur != prev && valid) ? 1.f : 0.f;
        if (valid) acc += srow[t];
    }
    #pragma unroll
    for (int o = 16; o; o >>= 1) acc += __shfl_xor_sync(0xFFFFFFFFu, acc, o);
    __shared__ float sh[32];
    int wid = threadIdx.x >> 5;
    if ((threadIdx.x & 31) == 0) sh[wid] = acc;
    __syncthreads();
    if (threadIdx.x == 0) {
        float s = 0.f;
        int nw = blockDim.x >> 5;
        for (int w = 0; w < nw; w++) s += sh[w];
        score_out[b] = s;
    }
}

extern "C" void kernel_launch(void* const* d_in, const int* in_sizes, int n_in,
                              void* d_out, int out_size) {
    const float* feat    = (const float*)d_in[0];
    const int*   lengths = (const int*)d_in[1];

    int B = in_sizes[1];
    int T = (out_size - B) / (2 * B);          // out = tokens(B*T) + keep(B*T) + scores(B)
    int V = (int)((long long)in_sizes[0] / ((long long)B * T));
    int rows = B * T;

    float* out   = (float*)d_out;
    float* tok   = out;
    float* keep  = out + (size_t)rows;
    float* score = out + 2 * (size_t)rows;

    if (V == 128 && (T % 64) == 0 && B <= 4096) {
        int blocks = rows / 64;                // 4096 for this shape
        ctc_fused_tma<<<blocks, 256>>>(feat, lengths, tok, keep, score, T, T / 64);
    } else {
        ctc_pass1_gen<<<(rows + 7) / 8, 256>>>(feat, tok, rows, V);
        ctc_pass2_gen<<<B, 256>>>(tok, lengths, keep, score, T);
    }
}

// round 12
// speedup vs baseline: 1.1388x; 1.1388x over previous
#include <cuda_runtime.h>
#include <cuda_bf16.h>
#include <math.h>

// Fallback scratch + per-batch accumulation state (zero-init; finalizer
// restores zeros each run so graph replays stay deterministic).
__device__ float g_maxscore[1 << 19];
__device__ float g_score_part[4096];
__device__ unsigned g_count[4096];

__device__ __forceinline__ unsigned f2ord(float x) {
    unsigned b = __float_as_uint(x);
    return (b & 0x80000000u) ? ~b : (b | 0x80000000u);
}
__device__ __forceinline__ float ord2f(unsigned u) {
    return __uint_as_float((u & 0x80000000u) ? (u ^ 0x80000000u) : ~u);
}

// Exact warp argmax (first index) over 128 values held as float4/lane.
__device__ __forceinline__ int warp_argmax128(float4 v, int lane, unsigned* Mu_out) {
    float m = v.x; int mi = 0;
    if (v.y > m) { m = v.y; mi = 1; }
    if (v.z > m) { m = v.z; mi = 2; }
    if (v.w > m) { m = v.w; mi = 3; }
    mi += lane * 4;
    unsigned mu = f2ord(m);
    unsigned Mu = __reduce_max_sync(0xFFFFFFFFu, mu);
    unsigned cand = (mu == Mu) ? (unsigned)mi : 0xFFFFFFFFu;
    *Mu_out = Mu;
    return (int)__reduce_min_sync(0xFFFFFFFFu, cand);
}

// ---------------------------------------------------------------------------
// Fused kernel (V=128, T%64==0): block = 256 threads = 8 warps = 64 rows
// (8 rows/warp -> MLP 8, best measured). Streaming (__ldcs) front-batched
// loads; exact two-REDUX argmax; unshifted exp + fixed-point REDUX.ADD.
// keep via smem tokens; boundary prev recomputed (1 row / 64).
// score finalize: scoped release/acquire atomics ONLY (no MEMBAR.GPU),
// self-resetting globals -> graph-replay safe, single kernel launch.
// ---------------------------------------------------------------------------
__global__ void __launch_bounds__(256) ctc_fused_v128(
    const float* __restrict__ feat, const int* __restrict__ lengths,
    float* __restrict__ tok_out, float* __restrict__ keep_out,
    float* __restrict__ score_out, int T, int blocksPerBatch)
{
    __shared__ int   s_tok[65];               // [0] = prev token entering block
    __shared__ float s_score;
    const int tid  = threadIdx.x;
    const int lane = tid & 31;
    const int w    = tid >> 5;
    const int R    = blockIdx.x * 64;         // first row of block
    const int b    = R / T;                   // T%64==0 -> whole block in batch b
    const int tb   = R - b * T;               // frame index of block start
    const float4* f4 = reinterpret_cast<const float4*>(feat);
    const int row0 = R + w * 8;

    if (tid == 0) s_score = 0.f;

    // Front-batched streaming loads: 8 rows per warp.
    float4 v[8];
    #pragma unroll
    for (int r = 0; r < 8; r++)
        v[r] = __ldcs(&f4[(size_t)(row0 + r) * 32 + lane]);

    const int len = lengths[b];

    // Boundary token (row R-1), warp 0. BLANK at batch start.
    if (w == 0) {
        int bt = 0;
        if (tb != 0) {
            unsigned Mu;
            bt = warp_argmax128(__ldcs(&f4[(size_t)(R - 1) * 32 + lane]), lane, &Mu);
        }
        if (lane == 0) s_tok[0] = bt;
    }

    const int nvalid = len - (tb + w * 8);    // rows [0,nvalid) of group valid
    float acc = 0.f;
    #pragma unroll
    for (int r = 0; r < 8; r++) {
        unsigned Mu;
        int token = warp_argmax128(v[r], lane, &Mu);
        if (lane == 0) s_tok[1 + w * 8 + r] = token;

        if (r < nvalid) {                     // warp-uniform
            // unshifted exp; lane partial -> fixed point (x 2^16); int REDUX
            float s = __expf(v[r].x) + __expf(v[r].y) +
                      __expf(v[r].z) + __expf(v[r].w);
            unsigned fx = (unsigned)(s * 65536.0f);
            unsigned S = __reduce_add_sync(0xFFFFFFFFu, fx);
            // max(log_softmax) = M - log(S * 2^-16) = M - log(S) + 16 ln2
            acc += ord2f(Mu) - __logf((float)S) + 11.0903548889591f;
        }
    }
    if (lane == 0 && nvalid > 0) atomicAdd(&s_score, acc);

    __syncthreads();

    // tok + keep for the block's 64 rows.
    if (tid < 64) {
        int cur  = s_tok[1 + tid];
        int prev = s_tok[tid];
        int t = tb + tid;
        tok_out[R + tid]  = (float)cur;
        keep_out[R + tid] = (cur != 0 && cur != prev && t < len) ? 1.f : 0.f;
    }

    // Per-batch score finalize with scoped atomics (no MEMBAR.GPU):
    //   red.release  : this block's partial visible before counter bump
    //   atom.acq_rel : last arrival acquires all released partials
    if (tid == 0) {
        asm volatile("red.release.gpu.global.add.f32 [%0], %1;"
                     :: "l"(&g_score_part[b]), "f"(s_score) : "memory");
        unsigned old;
        asm volatile("atom.acq_rel.gpu.global.add.u32 %0, [%1], 1;"
                     : "=r"(old) : "l"(&g_count[b]) : "memory");
        if (old == (unsigned)(blocksPerBatch - 1)) {
            float total;
            asm volatile("ld.acquire.gpu.global.f32 %0, [%1];"
                         : "=f"(total) : "l"(&g_score_part[b]) : "memory");
            score_out[b] = total;
            *((volatile float*)&g_score_part[b]) = 0.f;   // restore for replay
            *((volatile unsigned*)&g_count[b])   = 0u;
        }
    }
}

// ---------------------------------------------------------------------------
// Generic fallbacks (any V / T). Not expected to run for this shape.
// ---------------------------------------------------------------------------
__global__ void ctc_pass1_gen(const float* __restrict__ feat,
                              float* __restrict__ tok_out,
                              int rows, int V) {
    int warp = (blockIdx.x * blockDim.x + threadIdx.x) >> 5;
    int lane = threadIdx.x & 31;
    if (warp >= rows) return;
    const float* row = feat + (size_t)warp * V;

    float m = -INFINITY; int mi = 0;
    for (int i = lane; i < V; i += 32) {
        float x = row[i];
        if (x > m) { m = x; mi = i; }
    }
    #pragma unroll
    for (int o = 16; o; o >>= 1) {
        float om = __shfl_xor_sync(0xFFFFFFFFu, m, o);
        int   oi = __shfl_xor_sync(0xFFFFFFFFu, mi, o);
        if (om > m || (om == m && oi < mi)) { m = om; mi = oi; }
    }
    float s = 0.f;
    for (int i = lane; i < V; i += 32) s += __expf(row[i] - m);
    #pragma unroll
    for (int o = 16; o; o >>= 1) s += __shfl_xor_sync(0xFFFFFFFFu, s, o);
    if (lane == 0) { tok_out[warp] = (float)mi; g_maxscore[warp] = -__logf(s); }
}

__global__ void ctc_pass2_gen(const float* __restrict__ tok,
                              const int* __restrict__ lengths,
                              float* __restrict__ keep_out,
                              float* __restrict__ score_out,
                              int T) {
    int b = blockIdx.x;
    int len = lengths[b];
    const float* trow = tok + (size_t)b * T;
    float* krow = keep_out + (size_t)b * T;
    const float* srow = g_maxscore + (size_t)b * T;

    float acc = 0.f;
    for (int t = threadIdx.x; t < T; t += blockDim.x) {
        int cur  = (int)trow[t];
        int prev = (t == 0) ? 0 : (int)trow[t - 1];
        bool valid = (t < len);
        krow[t] = (cur != 0 && cur != prev && valid) ? 1.f : 0.f;
        if (valid) acc += srow[t];
    }
    #pragma unroll
    for (int o = 16; o; o >>= 1) acc += __shfl_xor_sync(0xFFFFFFFFu, acc, o);
    __shared__ float sh[32];
    int wid = threadIdx.x >> 5;
    if ((threadIdx.x & 31) == 0) sh[wid] = acc;
    __syncthreads();
    if (threadIdx.x == 0) {
        float s = 0.f;
        int nw = blockDim.x >> 5;
        for (int w = 0; w < nw; w++) s += sh[w];
        score_out[b] = s;
    }
}

extern "C" void kernel_launch(void* const* d_in, const int* in_sizes, int n_in,
                              void* d_out, int out_size) {
    const float* feat    = (const float*)d_in[0];
    const int*   lengths = (const int*)d_in[1];

    int B = in_sizes[1];
    int T = (out_size - B) / (2 * B);          // out = tokens(B*T) + keep(B*T) + scores(B)
    int V = (int)((long long)in_sizes[0] / ((long long)B * T));
    int rows = B * T;

    float* out   = (float*)d_out;
    float* tok   = out;
    float* keep  = out + (size_t)rows;
    float* score = out + 2 * (size_t)rows;

    if (V == 128 && (T % 64) == 0 && B <= 4096) {
        int blocks = rows / 64;                // 4096 for this shape
        ctc_fused_v128<<<blocks, 256>>>(feat, lengths, tok, keep, score, T, T / 64);
    } else {
        ctc_pass1_gen<<<(rows + 7) / 8, 256>>>(feat, tok, rows, V);
        ctc_pass2_gen<<<B, 256>>>(tok, lengths, keep, score, T);
    }
}